// round 7
// baseline (speedup 1.0000x reference)
#include <cuda_runtime.h>
#include <math.h>

// AttFusion: out[g,c,s] = sum_m softmax_m(<x0,xm>_c / 16) * x[m,c,s]
// x: [28, 256, 8448] fp32; out: [8, 256, 8448] fp32.
//
// R7: T_POS=64 (vs 32): halves barrier/softmax overhead per byte streamed
// while the pass1->pass2 L2 reuse window (~90 MB) stays under the 126 MB L2.
// Warp = 2 channel rows x 16 position-lanes -> 4 full 128B lines per LDG.128.
// Output uses __stwt streaming stores so stores don't evict the L2 slab.

#define C_DIM   256
#define S_DIM   8448            // 48*176, divisible by 64
#define T_POS   64              // s positions per block
#define N_MAX   5
#define N_GROUP 8
#define NWARPS  8
#define C_PER_W 32              // channels per warp (2 rows x 16 iters)

__device__ __constant__ int c_off[N_GROUP] = {0, 2, 5, 9, 14, 17, 19, 23};
__device__ __constant__ int c_len[N_GROUP] = {2, 3, 4, 5, 3, 2, 4, 5};

__global__ __launch_bounds__(256, 4)
void attfusion_kernel(const float* __restrict__ x, float* __restrict__ out) {
    __shared__ float red[N_MAX][NWARPS][T_POS];  // 10 KB partial dots
    __shared__ float wsm[N_MAX][T_POS];          // softmax weights

    const int g    = blockIdx.y;
    const int n    = c_len[g];
    const int off  = c_off[g];
    const int s0   = blockIdx.x * T_POS;
    const int tid  = threadIdx.x;
    const int lane = tid & 31;
    const int warp = tid >> 5;
    const int pos4 = lane & 15;              // position quad: covers 4*pos4..+3
    const int rowg = lane >> 4;              // channel sub-row 0..1
    const int c0   = warp * C_PER_W;

    const size_t mstride = (size_t)C_DIM * S_DIM;
    const float* xb = x + (size_t)(off * C_DIM + c0 + rowg) * S_DIM + s0 + pos4 * 4;

    // ---- Pass 1: partial dots over this thread's 16 channels ----
    float p[N_MAX][4];
#pragma unroll
    for (int m = 0; m < N_MAX; m++)
#pragma unroll
        for (int j = 0; j < 4; j++) p[m][j] = 0.0f;

    {
        const float* ptr = xb;
#pragma unroll 2
        for (int kk = 0; kk < 16; kk++) {     // channels c0 + rowg + 2*kk
            float4 xv[N_MAX];
#pragma unroll
            for (int m = 0; m < N_MAX; m++)
                if (m < n)
                    xv[m] = *reinterpret_cast<const float4*>(ptr + m * mstride);
#pragma unroll
            for (int m = 0; m < N_MAX; m++) {
                if (m < n) {
                    p[m][0] += xv[0].x * xv[m].x;
                    p[m][1] += xv[0].y * xv[m].y;
                    p[m][2] += xv[0].z * xv[m].z;
                    p[m][3] += xv[0].w * xv[m].w;
                }
            }
            ptr += 2 * S_DIM;
        }
    }

    // combine the 2 channel sub-rows within the warp (rowg = lane bit 4)
#pragma unroll
    for (int m = 0; m < N_MAX; m++) {
        if (m < n) {
#pragma unroll
            for (int j = 0; j < 4; j++)
                p[m][j] += __shfl_down_sync(0xffffffffu, p[m][j], 16);
        }
    }
    if (rowg == 0) {                          // lanes 0..15 hold the sums
#pragma unroll
        for (int m = 0; m < N_MAX; m++)
            if (m < n)
                *reinterpret_cast<float4*>(&red[m][warp][pos4 * 4]) =
                    make_float4(p[m][0], p[m][1], p[m][2], p[m][3]);
    }
    __syncthreads();

    // ---- Cross-warp reduce + softmax: one thread per s position ----
    if (tid < T_POS) {
        float d[N_MAX];
#pragma unroll
        for (int m = 0; m < N_MAX; m++) {
            if (m < n) {
                float a = 0.0f;
#pragma unroll
                for (int w = 0; w < NWARPS; w++) a += red[m][w][tid];
                d[m] = a * 0.0625f;           // 1/sqrt(256)
            } else {
                d[m] = -1e30f;
            }
        }
        float mx = d[0];
#pragma unroll
        for (int m = 1; m < N_MAX; m++) mx = fmaxf(mx, d[m]);
        float e[N_MAX], sumv = 0.0f;
#pragma unroll
        for (int m = 0; m < N_MAX; m++)
            if (m < n) { e[m] = __expf(d[m] - mx); sumv += e[m]; }
        const float inv = 1.0f / sumv;
#pragma unroll
        for (int m = 0; m < N_MAX; m++)
            if (m < n) wsm[m][tid] = e[m] * inv;
    }
    __syncthreads();

    // ---- Pass 2: weighted sum. Slab is L2-hot; streaming stores ----
    float4 wv[N_MAX];
#pragma unroll
    for (int m = 0; m < N_MAX; m++)
        if (m < n)
            wv[m] = *reinterpret_cast<const float4*>(&wsm[m][pos4 * 4]);

    {
        const float* ptr = xb;
        float* optr = out + (size_t)(g * C_DIM + c0 + rowg) * S_DIM + s0 + pos4 * 4;
#pragma unroll 2
        for (int kk = 0; kk < 16; kk++) {
            float4 xv[N_MAX];
#pragma unroll
            for (int m = 0; m < N_MAX; m++)
                if (m < n)
                    xv[m] = *reinterpret_cast<const float4*>(ptr + m * mstride);
            float4 acc = make_float4(0.f, 0.f, 0.f, 0.f);
#pragma unroll
            for (int m = 0; m < N_MAX; m++) {
                if (m < n) {
                    acc.x += wv[m].x * xv[m].x;
                    acc.y += wv[m].y * xv[m].y;
                    acc.z += wv[m].z * xv[m].z;
                    acc.w += wv[m].w * xv[m].w;
                }
            }
            __stwt(reinterpret_cast<float4*>(optr), acc);  // evict-first store
            ptr  += 2 * S_DIM;
            optr += 2 * S_DIM;
        }
    }
}

extern "C" void kernel_launch(void* const* d_in, const int* in_sizes, int n_in,
                              void* d_out, int out_size) {
    const float* x = (const float*)d_in[0];
    float* out = (float*)d_out;

    dim3 grid(S_DIM / T_POS, N_GROUP);        // 132 x 8 = 1056 blocks
    attfusion_kernel<<<grid, 256>>>(x, out);
}

// round 8
// speedup vs baseline: 1.2465x; 1.2465x over previous
#include <cuda_runtime.h>
#include <math.h>

// AttFusion: out[g,c,s] = sum_m softmax_m(<x0,xm>_c / 16) * x[m,c,s]
// x: [28, 256, 8448] fp32; out: [8, 256, 8448] fp32.
//
// R8 = R6 (T_POS=32, pass2 L2-hot, traffic ~= 323MB floor) minus the latency
// bubbles: single __syncthreads per block; softmax computed redundantly by
// every thread for its own 4 positions (no 32-thread serial phase, no 2nd
// barrier); pass-2 first chunk loads issued before the weight math; __ldlu
// on pass-2 reads (exact last use) and __stwt on stores for L2 hygiene.

#define C_DIM   256
#define S_DIM   8448            // 48*176, divisible by 32
#define T_POS   32              // s positions per block
#define N_MAX   5
#define N_GROUP 8
#define NWARPS  8
#define C_PER_W 32              // channels per warp (4 rows x 8 iters)

__device__ __constant__ int c_off[N_GROUP] = {0, 2, 5, 9, 14, 17, 19, 23};
__device__ __constant__ int c_len[N_GROUP] = {2, 3, 4, 5, 3, 2, 4, 5};

__global__ __launch_bounds__(256, 4)
void attfusion_kernel(const float* __restrict__ x, float* __restrict__ out) {
    __shared__ float red[N_MAX][NWARPS][T_POS];  // 5 KB partial dots

    const int g    = blockIdx.y;
    const int n    = c_len[g];
    const int off  = c_off[g];
    const int s0   = blockIdx.x * T_POS;
    const int tid  = threadIdx.x;
    const int lane = tid & 31;
    const int warp = tid >> 5;
    const int lo3  = lane & 7;                // position quad 4*lo3 .. 4*lo3+3
    const int rowg = lane >> 3;               // channel sub-row 0..3
    const int c0   = warp * C_PER_W;

    const size_t mstride = (size_t)C_DIM * S_DIM;
    const float* xb = x + (size_t)(off * C_DIM + c0 + rowg) * S_DIM + s0 + lo3 * 4;

    // ---- Pass 1: partial dots over this thread's 8 channels ----
    float p[N_MAX][4];
#pragma unroll
    for (int m = 0; m < N_MAX; m++)
#pragma unroll
        for (int j = 0; j < 4; j++) p[m][j] = 0.0f;

    {
        const float* ptr = xb;
#pragma unroll 2
        for (int kk = 0; kk < 8; kk++) {       // channels c0 + rowg + 4*kk
            float4 xv[N_MAX];
#pragma unroll
            for (int m = 0; m < N_MAX; m++)
                if (m < n)
                    xv[m] = *reinterpret_cast<const float4*>(ptr + m * mstride);
#pragma unroll
            for (int m = 0; m < N_MAX; m++) {
                if (m < n) {
                    p[m][0] += xv[0].x * xv[m].x;
                    p[m][1] += xv[0].y * xv[m].y;
                    p[m][2] += xv[0].z * xv[m].z;
                    p[m][3] += xv[0].w * xv[m].w;
                }
            }
            ptr += 4 * S_DIM;
        }
    }

    // combine the 4 channel sub-rows within the warp (rowg = lane bits 3-4)
#pragma unroll
    for (int m = 0; m < N_MAX; m++) {
        if (m < n) {
#pragma unroll
            for (int j = 0; j < 4; j++) {
                p[m][j] += __shfl_down_sync(0xffffffffu, p[m][j], 16);
                p[m][j] += __shfl_down_sync(0xffffffffu, p[m][j], 8);
            }
        }
    }
    if (rowg == 0) {                           // lanes 0..7 hold the sums
#pragma unroll
        for (int m = 0; m < N_MAX; m++)
            if (m < n)
                *reinterpret_cast<float4*>(&red[m][warp][lo3 * 4]) =
                    make_float4(p[m][0], p[m][1], p[m][2], p[m][3]);
    }
    __syncthreads();                           // the ONLY barrier

    // ---- Prefetch pass-2 chunk 0 (independent of weights) ----
    float4 xv0[N_MAX];
#pragma unroll
    for (int m = 0; m < N_MAX; m++)
        if (m < n)
            xv0[m] = __ldlu(reinterpret_cast<const float4*>(xb + m * mstride));

    // ---- Redundant per-thread softmax for this thread's 4 positions ----
    float4 dv[N_MAX];
#pragma unroll
    for (int m = 0; m < N_MAX; m++) {
        if (m < n) {
            float4 a = make_float4(0.f, 0.f, 0.f, 0.f);
#pragma unroll
            for (int w = 0; w < NWARPS; w++) {
                const float4 r = *reinterpret_cast<const float4*>(&red[m][w][lo3 * 4]);
                a.x += r.x; a.y += r.y; a.z += r.z; a.w += r.w;
            }
            dv[m] = make_float4(a.x * 0.0625f, a.y * 0.0625f,
                                a.z * 0.0625f, a.w * 0.0625f);
        } else {
            dv[m] = make_float4(-1e30f, -1e30f, -1e30f, -1e30f);
        }
    }
    float4 mx = dv[0];
#pragma unroll
    for (int m = 1; m < N_MAX; m++) {
        mx.x = fmaxf(mx.x, dv[m].x); mx.y = fmaxf(mx.y, dv[m].y);
        mx.z = fmaxf(mx.z, dv[m].z); mx.w = fmaxf(mx.w, dv[m].w);
    }
    float4 wv[N_MAX];
    float4 sum4 = make_float4(0.f, 0.f, 0.f, 0.f);
#pragma unroll
    for (int m = 0; m < N_MAX; m++) {
        if (m < n) {
            wv[m] = make_float4(__expf(dv[m].x - mx.x), __expf(dv[m].y - mx.y),
                                __expf(dv[m].z - mx.z), __expf(dv[m].w - mx.w));
            sum4.x += wv[m].x; sum4.y += wv[m].y;
            sum4.z += wv[m].z; sum4.w += wv[m].w;
        }
    }
    const float4 inv = make_float4(1.0f / sum4.x, 1.0f / sum4.y,
                                   1.0f / sum4.z, 1.0f / sum4.w);
#pragma unroll
    for (int m = 0; m < N_MAX; m++) {
        if (m < n) {
            wv[m].x *= inv.x; wv[m].y *= inv.y;
            wv[m].z *= inv.z; wv[m].w *= inv.w;
        }
    }

    // ---- Pass 2: weighted sum; chunk 0 from prefetch, rest streamed ----
    float* ob = out + (size_t)(g * C_DIM + c0 + rowg) * S_DIM + s0 + lo3 * 4;
    {
        float4 acc = make_float4(0.f, 0.f, 0.f, 0.f);
#pragma unroll
        for (int m = 0; m < N_MAX; m++) {
            if (m < n) {
                acc.x += wv[m].x * xv0[m].x;
                acc.y += wv[m].y * xv0[m].y;
                acc.z += wv[m].z * xv0[m].z;
                acc.w += wv[m].w * xv0[m].w;
            }
        }
        __stwt(reinterpret_cast<float4*>(ob), acc);
    }
    {
        const float* ptr = xb + 4 * S_DIM;
        float* optr = ob + 4 * S_DIM;
#pragma unroll 2
        for (int kk = 1; kk < 8; kk++) {
            float4 xv[N_MAX];
#pragma unroll
            for (int m = 0; m < N_MAX; m++)
                if (m < n)
                    xv[m] = __ldlu(reinterpret_cast<const float4*>(ptr + m * mstride));
            float4 acc = make_float4(0.f, 0.f, 0.f, 0.f);
#pragma unroll
            for (int m = 0; m < N_MAX; m++) {
                if (m < n) {
                    acc.x += wv[m].x * xv[m].x;
                    acc.y += wv[m].y * xv[m].y;
                    acc.z += wv[m].z * xv[m].z;
                    acc.w += wv[m].w * xv[m].w;
                }
            }
            __stwt(reinterpret_cast<float4*>(optr), acc);
            ptr  += 4 * S_DIM;
            optr += 4 * S_DIM;
        }
    }
}

extern "C" void kernel_launch(void* const* d_in, const int* in_sizes, int n_in,
                              void* d_out, int out_size) {
    const float* x = (const float*)d_in[0];
    float* out = (float*)d_out;

    dim3 grid(S_DIM / T_POS, N_GROUP);         // 264 x 8 = 2112 blocks
    attfusion_kernel<<<grid, 256>>>(x, out);
}

// round 9
// speedup vs baseline: 1.3119x; 1.0525x over previous
#include <cuda_runtime.h>
#include <math.h>

// AttFusion: out[g,c,s] = sum_m softmax_m(<x0,xm>_c / 16) * x[m,c,s]
// x: [28, 256, 8448] fp32; out: [8, 256, 8448] fp32.
//
// R9: T_POS=32 two-pass (pass-2 L2-hot, ~300 MB traffic), ONE barrier.
// Inter-pass softmax is per-WARP redundant: lane = position, 8*n scalar LDS
// + n exp per lane, then n*4 shuffles broadcast the weights to the float4
// lanes. Chunk-0 of pass 2 prefetched before the weight math. __ldlu on
// pass-2 reads (exact last use), __stwt on stores (L2 hygiene).

#define C_DIM   256
#define S_DIM   8448            // 48*176, divisible by 32
#define T_POS   32              // s positions per block
#define N_MAX   5
#define N_GROUP 8
#define NWARPS  8
#define C_PER_W 32              // channels per warp (4 rows x 8 iters)
#define FULL    0xffffffffu

__device__ __constant__ int c_off[N_GROUP] = {0, 2, 5, 9, 14, 17, 19, 23};
__device__ __constant__ int c_len[N_GROUP] = {2, 3, 4, 5, 3, 2, 4, 5};

__global__ __launch_bounds__(256, 4)
void attfusion_kernel(const float* __restrict__ x, float* __restrict__ out) {
    __shared__ float red[N_MAX][NWARPS][T_POS];  // 5 KB partial dots

    const int g    = blockIdx.y;
    const int n    = c_len[g];
    const int off  = c_off[g];
    const int s0   = blockIdx.x * T_POS;
    const int tid  = threadIdx.x;
    const int lane = tid & 31;
    const int warp = tid >> 5;
    const int lo3  = lane & 7;                // position quad 4*lo3 .. 4*lo3+3
    const int rowg = lane >> 3;               // channel sub-row 0..3
    const int c0   = warp * C_PER_W;

    const size_t mstride = (size_t)C_DIM * S_DIM;
    const float* xb = x + (size_t)(off * C_DIM + c0 + rowg) * S_DIM + s0 + lo3 * 4;

    // ---- Pass 1: partial dots over this thread's 8 channels ----
    float p[N_MAX][4];
#pragma unroll
    for (int m = 0; m < N_MAX; m++)
#pragma unroll
        for (int j = 0; j < 4; j++) p[m][j] = 0.0f;

    {
        const float* ptr = xb;
#pragma unroll 2
        for (int kk = 0; kk < 8; kk++) {       // channels c0 + rowg + 4*kk
            float4 xv[N_MAX];
#pragma unroll
            for (int m = 0; m < N_MAX; m++)
                if (m < n)
                    xv[m] = *reinterpret_cast<const float4*>(ptr + m * mstride);
#pragma unroll
            for (int m = 0; m < N_MAX; m++) {
                if (m < n) {
                    p[m][0] += xv[0].x * xv[m].x;
                    p[m][1] += xv[0].y * xv[m].y;
                    p[m][2] += xv[0].z * xv[m].z;
                    p[m][3] += xv[0].w * xv[m].w;
                }
            }
            ptr += 4 * S_DIM;
        }
    }

    // combine the 4 channel sub-rows within the warp (rowg = lane bits 3-4)
#pragma unroll
    for (int m = 0; m < N_MAX; m++) {
        if (m < n) {
#pragma unroll
            for (int j = 0; j < 4; j++) {
                p[m][j] += __shfl_down_sync(FULL, p[m][j], 16);
                p[m][j] += __shfl_down_sync(FULL, p[m][j], 8);
            }
        }
    }
    if (rowg == 0) {                           // lanes 0..7 hold the sums
#pragma unroll
        for (int m = 0; m < N_MAX; m++)
            if (m < n)
                *reinterpret_cast<float4*>(&red[m][warp][lo3 * 4]) =
                    make_float4(p[m][0], p[m][1], p[m][2], p[m][3]);
    }
    __syncthreads();                           // the ONLY barrier

    // ---- Prefetch pass-2 chunk 0 (independent of weights) ----
    float4 xv0[N_MAX];
#pragma unroll
    for (int m = 0; m < N_MAX; m++)
        if (m < n)
            xv0[m] = __ldlu(reinterpret_cast<const float4*>(xb + m * mstride));

    // ---- Per-warp redundant softmax: lane = position ----
    float wl[N_MAX];                           // weight for position `lane`
    {
        float d[N_MAX];
#pragma unroll
        for (int m = 0; m < N_MAX; m++) {
            if (m < n) {
                float a = 0.0f;
#pragma unroll
                for (int w = 0; w < NWARPS; w++) a += red[m][w][lane];
                d[m] = a * 0.0625f;            // 1/sqrt(256)
            } else {
                d[m] = -1e30f;
            }
        }
        float mx = d[0];
#pragma unroll
        for (int m = 1; m < N_MAX; m++) mx = fmaxf(mx, d[m]);
        float sumv = 0.0f;
#pragma unroll
        for (int m = 0; m < N_MAX; m++) {
            if (m < n) { wl[m] = __expf(d[m] - mx); sumv += wl[m]; }
            else wl[m] = 0.0f;
        }
        const float inv = 1.0f / sumv;
#pragma unroll
        for (int m = 0; m < N_MAX; m++) wl[m] *= inv;
    }

    // distribute: this thread's 4 positions are lanes 4*lo3 .. 4*lo3+3
    float4 wv[N_MAX];
#pragma unroll
    for (int m = 0; m < N_MAX; m++) {
        if (m < n) {
            wv[m].x = __shfl_sync(FULL, wl[m], 4 * lo3 + 0);
            wv[m].y = __shfl_sync(FULL, wl[m], 4 * lo3 + 1);
            wv[m].z = __shfl_sync(FULL, wl[m], 4 * lo3 + 2);
            wv[m].w = __shfl_sync(FULL, wl[m], 4 * lo3 + 3);
        }
    }

    // ---- Pass 2: weighted sum; chunk 0 from prefetch, rest streamed ----
    float* ob = out + (size_t)(g * C_DIM + c0 + rowg) * S_DIM + s0 + lo3 * 4;
    {
        float4 acc = make_float4(0.f, 0.f, 0.f, 0.f);
#pragma unroll
        for (int m = 0; m < N_MAX; m++) {
            if (m < n) {
                acc.x += wv[m].x * xv0[m].x;
                acc.y += wv[m].y * xv0[m].y;
                acc.z += wv[m].z * xv0[m].z;
                acc.w += wv[m].w * xv0[m].w;
            }
        }
        __stwt(reinterpret_cast<float4*>(ob), acc);
    }
    {
        const float* ptr = xb + 4 * S_DIM;
        float* optr = ob + 4 * S_DIM;
#pragma unroll 2
        for (int kk = 1; kk < 8; kk++) {
            float4 xv[N_MAX];
#pragma unroll
            for (int m = 0; m < N_MAX; m++)
                if (m < n)
                    xv[m] = __ldlu(reinterpret_cast<const float4*>(ptr + m * mstride));
            float4 acc = make_float4(0.f, 0.f, 0.f, 0.f);
#pragma unroll
            for (int m = 0; m < N_MAX; m++) {
                if (m < n) {
                    acc.x += wv[m].x * xv[m].x;
                    acc.y += wv[m].y * xv[m].y;
                    acc.z += wv[m].z * xv[m].z;
                    acc.w += wv[m].w * xv[m].w;
                }
            }
            __stwt(reinterpret_cast<float4*>(optr), acc);
            ptr  += 4 * S_DIM;
            optr += 4 * S_DIM;
        }
    }
}

extern "C" void kernel_launch(void* const* d_in, const int* in_sizes, int n_in,
                              void* d_out, int out_size) {
    const float* x = (const float*)d_in[0];
    float* out = (float*)d_out;

    dim3 grid(S_DIM / T_POS, N_GROUP);         // 264 x 8 = 2112 blocks
    attfusion_kernel<<<grid, 256>>>(x, out);
}